// round 12
// baseline (speedup 1.0000x reference)
#include <cuda_runtime.h>
#include <cuda_fp16.h>
#include <math.h>
#include <stdint.h>

// Problem constants
#define B_   8
#define N_   1024
#define DIM_ 768
#define H_   8
#define HD_  96
#define CHUNK_B 2   // batches per pipeline chunk (L2 residency of S/P)

// ---------------- scratch (device globals; no allocation allowed) ----------
__device__ __align__(256) __half g_qh[B_*H_*N_*HD_];   // (B,H,N,96) fp16
__device__ __align__(256) __half g_kh[B_*H_*N_*HD_];
__device__ __align__(256) __half g_vh[B_*H_*N_*HD_];
__device__ __align__(256) __half g_vt[B_*H_*HD_*N_];   // (B,H,96,N) fp16
__device__ __align__(256) __half g_wt[DIM_*DIM_];      // proj W^T [n][k] fp16
__device__ __align__(256) __half g_s[67108864];        // S logits (B,H,N,N) fp16
__device__ __align__(256) __half g_p[67108864];        // P (post softmax+mix) fp16
__device__ __align__(256) __half g_ctx[B_*N_*DIM_];    // (B,N,768) fp16

// ---------------------------------------------------------------------------
__device__ __forceinline__ void mma_f16(float* c, const uint32_t* a, const uint32_t* b) {
    asm volatile(
        "mma.sync.aligned.m16n8k16.row.col.f32.f16.f16.f32 "
        "{%0,%1,%2,%3}, {%4,%5,%6,%7}, {%8,%9}, {%0,%1,%2,%3};"
        : "+f"(c[0]), "+f"(c[1]), "+f"(c[2]), "+f"(c[3])
        : "r"(a[0]), "r"(a[1]), "r"(a[2]), "r"(a[3]), "r"(b[0]), "r"(b[1]));
}
__device__ __forceinline__ void ldm_x4(uint32_t* r, uint32_t saddr) {
    asm volatile("ldmatrix.sync.aligned.m8n8.x4.shared.b16 {%0,%1,%2,%3}, [%4];"
        : "=r"(r[0]), "=r"(r[1]), "=r"(r[2]), "=r"(r[3]) : "r"(saddr));
}
__device__ __forceinline__ void cp_async16(void* smem, const void* gmem) {
    uint32_t s = (uint32_t)__cvta_generic_to_shared(smem);
    asm volatile("cp.async.cg.shared.global [%0], [%1], 16;" :: "r"(s), "l"(gmem));
}
#define CP_COMMIT asm volatile("cp.async.commit_group;")
#define CP_WAIT2  asm volatile("cp.async.wait_group 2;")
#define CP_WAIT1  asm volatile("cp.async.wait_group 1;")
#define CP_WAIT0  asm volatile("cp.async.wait_group 0;")

// ---------------------------------------------------------------------------
// Kernel 1: 3x3 SAME conv on 16x16x3 token image + head split -> fp16
// ---------------------------------------------------------------------------
__global__ void conv_heads_kernel(const float* __restrict__ q,
                                  const float* __restrict__ k,
                                  const float* __restrict__ v,
                                  const float* __restrict__ w) {
    __shared__ float img[768];
    __shared__ float wt[81];
    int token = blockIdx.x;
    int which = blockIdx.y;
    int tid = threadIdx.x;

    const float* src = (which == 0) ? q : (which == 1) ? k : v;
    __half* dst = (which == 0) ? g_qh : (which == 1) ? g_kh : g_vh;

    const float* xp = src + (size_t)token * DIM_;
    for (int i = tid; i < 768; i += 256) img[i] = xp[i];
    if (tid < 81) wt[tid] = w[tid];
    __syncthreads();

    int s = tid >> 4, t = tid & 15;
    float acc0 = 0.f, acc1 = 0.f, acc2 = 0.f;
#pragma unroll
    for (int dy = 0; dy < 3; ++dy) {
        int ys = s + dy - 1;
        bool vy = ((unsigned)ys < 16u);
#pragma unroll
        for (int dx = 0; dx < 3; ++dx) {
            int xs = t + dx - 1;
            if (vy && ((unsigned)xs < 16u)) {
                int base = (ys * 16 + xs) * 3;
                int wb = (dy * 3 + dx) * 9;
#pragma unroll
                for (int ci = 0; ci < 3; ++ci) {
                    float pv = img[base + ci];
                    acc0 += pv * wt[wb + ci * 3 + 0];
                    acc1 += pv * wt[wb + ci * 3 + 1];
                    acc2 += pv * wt[wb + ci * 3 + 2];
                }
            }
        }
    }
    int b = token >> 10, n = token & 1023;
    float accs[3] = {acc0, acc1, acc2};
    int p = tid * 3;
#pragma unroll
    for (int co = 0; co < 3; ++co) {
        int pp = p + co;
        int h = pp / 96;
        int d = pp - h * 96;
        dst[(((size_t)b * H_ + h) * N_ + n) * HD_ + d] = __float2half_rn(accs[co]);
    }
}

// ---------------------------------------------------------------------------
// Kernel 2: batched tiled transpose: (batch,R,C) -> (batch,C,R), TI -> half
// ---------------------------------------------------------------------------
template<typename TI>
__global__ void transpose_kernel(const TI* __restrict__ in, __half* __restrict__ out,
                                 int R, int C) {
    __shared__ float t[32][33];
    int c0 = blockIdx.x * 32, r0 = blockIdx.y * 32;
    const TI* ip = in + (size_t)blockIdx.z * R * C;
    __half* op = out + (size_t)blockIdx.z * R * C;
    int x = threadIdx.x, y = threadIdx.y;
#pragma unroll
    for (int i = 0; i < 32; i += 8)
        t[y + i][x] = (float)ip[(size_t)(r0 + y + i) * C + c0 + x];
    __syncthreads();
#pragma unroll
    for (int i = 0; i < 32; i += 8)
        op[(size_t)(c0 + y + i) * R + r0 + x] = __float2half_rn(t[x][y + i]);
}

// ---------------------------------------------------------------------------
// FP16 NT GEMM (fp32 accum), 4-stage cp.async ring, ONE barrier per k-tile.
// C[m][n] = scale * sum_k A[m][k]*Bt[n][k] (+ bias[n]).
// 128 threads = 4 warps (2x2). CTA tile 128 x BN, warp tile 64 x WN (WN=BN/2).
// BK=32 halves. Smem rows stride 20 uints (80B) -> conflict-free ldmatrix.
// ---------------------------------------------------------------------------
template<int BN, bool HALF_OUT>
__global__ __launch_bounds__(128, 2)
void f16_gemm_nt(const __half* __restrict__ A, const __half* __restrict__ Bt,
                 void* __restrict__ Cv,
                 int K, int lda, int ldb, int ldc,
                 long long sA, long long sB, long long sCo, long long sCi,
                 float scale, const float* __restrict__ bias) {
    constexpr int WN = BN / 2;
    constexpr int NF = WN / 8;              // 8 (BN=128) or 6 (BN=96)
    constexpr int ASTRIDE = 128 * 20;
    constexpr int BSTRIDE = BN * 20;
    extern __shared__ __align__(16) uint32_t smraw[];
    uint32_t* As0 = smraw;                  // 4 stages x 128*20
    uint32_t* Bs0 = smraw + 4 * ASTRIDE;    // 4 stages x BN*20

    int z = blockIdx.z;
    A += (size_t)z * sA;
    Bt += (size_t)z * sB;
    size_t coff = (size_t)(z >> 3) * sCo + (size_t)(z & 7) * sCi;

    int tid = threadIdx.x;
    int lane = tid & 31, w = tid >> 5;
    int wm = w >> 1, wn = w & 1;
    int gid = lane >> 2, tig = lane & 3;
    int m0 = blockIdx.y * 128, n0 = blockIdx.x * BN;

    // per-lane ldmatrix offsets (bytes within tile)
    int lt = lane >> 3, lr = lane & 7;
    int a_lane_off = ((lt & 1) * 8 + lr) * 80 + (lt >> 1) * 16;
    int b_lane_off = ((lt >> 1) * 8 + lr) * 80 + (lt & 1) * 16;

    float acc[4][NF][4];
#pragma unroll
    for (int i = 0; i < 4; ++i)
#pragma unroll
        for (int j = 0; j < NF; ++j)
#pragma unroll
            for (int r = 0; r < 4; ++r) acc[i][j][r] = 0.f;

    int T = K >> 5;   // BK = 32 halves

    auto load_tile = [&](int t, int stg) {
        int k0 = t * 32;
        uint32_t* Asg = As0 + stg * ASTRIDE;
        uint32_t* Bsg = Bs0 + stg * BSTRIDE;
#pragma unroll
        for (int it = 0; it < 4; ++it) {
            int idx = tid + it * 128;
            int row = idx >> 2, c = idx & 3;          // c: 16B chunk = 8 halves
            cp_async16(&Asg[row * 20 + c * 4],
                       &A[(size_t)(m0 + row) * lda + k0 + c * 8]);
        }
#pragma unroll
        for (int it = 0; it < (BN * 4 + 127) / 128; ++it) {
            int idx = tid + it * 128;
            if (BN == 128 || idx < BN * 4) {
                int row = idx >> 2, c = idx & 3;
                cp_async16(&Bsg[row * 20 + c * 4],
                           &Bt[(size_t)(n0 + row) * ldb + k0 + c * 8]);
            }
        }
    };

    load_tile(0, 0); CP_COMMIT;
    if (T > 1) { load_tile(1, 1); CP_COMMIT; }

    for (int t = 0; t < T; ++t) {
        if (t + 2 < T) { load_tile(t + 2, (t + 2) & 3); CP_COMMIT; CP_WAIT2; }
        else if (t + 1 < T) { CP_WAIT1; }
        else { CP_WAIT0; }
        __syncthreads();

        int cur = t & 3;
        uint32_t abase = (uint32_t)__cvta_generic_to_shared(As0 + cur * ASTRIDE);
        uint32_t bbase = (uint32_t)__cvta_generic_to_shared(Bs0 + cur * BSTRIDE);
#pragma unroll
        for (int kk = 0; kk < 16; kk += 8) {   // 2 k-groups of 16 halves
            int kk4 = kk * 4;
            uint32_t a[4][4];
#pragma unroll
            for (int i = 0; i < 4; ++i)
                ldm_x4(a[i], abase + (wm * 64 + i * 16) * 80 + kk4 + a_lane_off);
            uint32_t bf[NF * 2];
#pragma unroll
            for (int p = 0; p < NF / 2; ++p)
                ldm_x4(&bf[p * 4], bbase + (wn * WN + p * 16) * 80 + kk4 + b_lane_off);
#pragma unroll
            for (int i = 0; i < 4; ++i)
#pragma unroll
                for (int j = 0; j < NF; ++j)
                    mma_f16(acc[i][j], a[i], &bf[j * 2]);
        }
        // no trailing barrier (4-stage ring makes it safe)
    }

    // direct epilogue
#pragma unroll
    for (int i = 0; i < 4; ++i) {
        int r = m0 + wm * 64 + i * 16 + gid;
#pragma unroll
        for (int j = 0; j < NF; ++j) {
            int cgl = n0 + wn * WN + j * 8 + tig * 2;
            float x0 = acc[i][j][0] * scale, y0 = acc[i][j][1] * scale;
            float x1 = acc[i][j][2] * scale, y1 = acc[i][j][3] * scale;
            if (bias) {
                float bx = bias[cgl], by = bias[cgl + 1];
                x0 += bx; y0 += by; x1 += bx; y1 += by;
            }
            if (HALF_OUT) {
                __half* C = (__half*)Cv + coff;
                *(__half2*)&C[(size_t)r * ldc + cgl] = __floats2half2_rn(x0, y0);
                *(__half2*)&C[(size_t)(r + 8) * ldc + cgl] = __floats2half2_rn(x1, y1);
            } else {
                float* C = (float*)Cv + coff;
                *(float2*)&C[(size_t)r * ldc + cgl] = make_float2(x0, y0);
                *(float2*)&C[(size_t)(r + 8) * ldc + cgl] = make_float2(x1, y1);
            }
        }
    }
}

// ---------------------------------------------------------------------------
// Fused softmax + 8x8 head mix + BN. Register-resident per-warp softmax.
// S/P passed as chunk-base pointers; one block (256 thr) per (b_local, n).
// ---------------------------------------------------------------------------
__global__ __launch_bounds__(256)
void softmax_mix_kernel(const __half* __restrict__ Sb, __half* __restrict__ Pb,
                        const float* __restrict__ rw, const float* __restrict__ rb,
                        const float* __restrict__ gamma, const float* __restrict__ beta,
                        const float* __restrict__ mean, const float* __restrict__ var) {
    __shared__ __half2 buf[8][512];
    __shared__ float Wm[8][8];
    __shared__ float Cm[8];
    int tid = threadIdx.x;
    int bn = blockIdx.x;
    int b = bn >> 10, n = bn & 1023;

    if (tid < 64) {
        int h = tid >> 3, g = tid & 7;
        float inv = gamma[g] * rsqrtf(var[g] + 1e-3f);
        Wm[h][g] = rw[h * 8 + g] * inv;
        if (h == 0) Cm[g] = (rb[g] - mean[g]) * inv + beta[g];
    }

    int w = tid >> 5, lane = tid & 31;
    size_t base = (size_t)b * 8388608 + (size_t)n * 1024;

    // load head w's row into registers: 4 uint4 = 16 half2 per lane
    const uint4* src = (const uint4*)(Sb + base + (size_t)w * 1048576);
    uint4 raw[4];
#pragma unroll
    for (int j = 0; j < 4; ++j) raw[j] = src[lane + j * 32];
    __half2* vh2 = (__half2*)raw;   // 16 half2, linear in m

    // max (fp16), reduce across warp
    __half2 m2 = vh2[0];
#pragma unroll
    for (int ii = 1; ii < 16; ++ii) m2 = __hmax2(m2, vh2[ii]);
#pragma unroll
    for (int o = 16; o > 0; o >>= 1) {
        uint32_t u = *(uint32_t*)&m2;
        u = __shfl_xor_sync(0xffffffffu, u, o);
        m2 = __hmax2(m2, *(__half2*)&u);
    }
    __half2 mx2 = __half2half2(__hmax(__low2half(m2), __high2half(m2)));
    const __half2 l2e = __float2half2_rn(1.44269504f);

    // exp in fp16 (ex2.f16x2), fp32 sum
    float s = 0.f;
#pragma unroll
    for (int ii = 0; ii < 16; ++ii) {
        __half2 e = h2exp2(__hmul2(__hsub2(vh2[ii], mx2), l2e));
        vh2[ii] = e;
        float2 f = __half22float2(e);
        s += f.x + f.y;
    }
#pragma unroll
    for (int o = 16; o > 0; o >>= 1) s += __shfl_xor_sync(0xffffffffu, s, o);
    __half2 inv2 = __float2half2_rn(1.0f / s);

    // normalize in fp16 (P is fp16 downstream anyway), store to smem
#pragma unroll
    for (int ii = 0; ii < 16; ++ii) vh2[ii] = __hmul2(vh2[ii], inv2);
    uint4* brow = (uint4*)&buf[w][0];
#pragma unroll
    for (int j = 0; j < 4; ++j) brow[lane + j * 32] = raw[j];
    __syncthreads();

    // mix heads in fp32, 4 columns (m = 4*tid..4*tid+3) per thread
    float4 p[8];
#pragma unroll
    for (int h = 0; h < 8; ++h) {
        float2 rawm = ((const float2*)&buf[h][0])[tid];   // 2 half2 = 4 halves
        __half2 lo = *(__half2*)&rawm.x, hi = *(__half2*)&rawm.y;
        float2 f0 = __half22float2(lo), f1 = __half22float2(hi);
        p[h] = make_float4(f0.x, f0.y, f1.x, f1.y);
    }
    float2* gout = (float2*)(Pb + base);                // 8B = 4 halves
#pragma unroll
    for (int g = 0; g < 8; ++g) {
        float c = Cm[g];
        float4 o = make_float4(c, c, c, c);
#pragma unroll
        for (int h = 0; h < 8; ++h) {
            float wv = Wm[h][g];
            o.x += p[h].x * wv; o.y += p[h].y * wv;
            o.z += p[h].z * wv; o.w += p[h].w * wv;
        }
        float2 st;
        *(__half2*)&st.x = __floats2half2_rn(o.x, o.y);
        *(__half2*)&st.y = __floats2half2_rn(o.z, o.w);
        gout[(size_t)g * 262144 + tid] = st;
    }
}

// ---------------------------------------------------------------------------
extern "C" void kernel_launch(void* const* d_in, const int* in_sizes, int n_in,
                              void* d_out, int out_size) {
    const float* q      = (const float*)d_in[0];
    const float* k      = (const float*)d_in[1];
    const float* v      = (const float*)d_in[2];
    const float* conv_w = (const float*)d_in[3];
    const float* rw     = (const float*)d_in[4];
    const float* rb     = (const float*)d_in[5];
    const float* gamma  = (const float*)d_in[6];
    const float* beta   = (const float*)d_in[7];
    const float* mean   = (const float*)d_in[8];
    const float* var    = (const float*)d_in[9];
    const float* pw     = (const float*)d_in[10];
    const float* pb     = (const float*)d_in[11];
    float* out = (float*)d_out;

    float scale = 1.0f / sqrtf((float)HD_);

    __half *qh, *kh, *vh, *vt, *wt, *sS, *pp, *ctx;
    cudaGetSymbolAddress((void**)&qh, g_qh);
    cudaGetSymbolAddress((void**)&kh, g_kh);
    cudaGetSymbolAddress((void**)&vh, g_vh);
    cudaGetSymbolAddress((void**)&vt, g_vt);
    cudaGetSymbolAddress((void**)&wt, g_wt);
    cudaGetSymbolAddress((void**)&sS, g_s);
    cudaGetSymbolAddress((void**)&pp, g_p);
    cudaGetSymbolAddress((void**)&ctx, g_ctx);

    const int SM128 = 4 * (128 + 128) * 20 * 4;   // 81920 B
    const int SM96  = 4 * (128 + 96) * 20 * 4;    // 71680 B
    cudaFuncSetAttribute(f16_gemm_nt<128, true>,
                         cudaFuncAttributeMaxDynamicSharedMemorySize, SM128);
    cudaFuncSetAttribute(f16_gemm_nt<96, true>,
                         cudaFuncAttributeMaxDynamicSharedMemorySize, SM96);
    cudaFuncSetAttribute(f16_gemm_nt<128, false>,
                         cudaFuncAttributeMaxDynamicSharedMemorySize, SM128);

    // 1. conv + head split (fp16 outputs)
    conv_heads_kernel<<<dim3(B_ * N_, 3), 256>>>(q, k, v, conv_w);

    // 2. transposes: V(half) -> (B,H,96,N) half, W(float) -> [n][k] half
    transpose_kernel<__half><<<dim3(HD_ / 32, N_ / 32, B_ * H_), dim3(32, 8)>>>(vh, vt, N_, HD_);
    transpose_kernel<float><<<dim3(DIM_ / 32, DIM_ / 32, 1), dim3(32, 8)>>>(pw, wt, DIM_, DIM_);

    // 3-5. chunked qk -> softmax -> av per CHUNK_B batches (S/P stay L2-hot)
    for (int b0 = 0; b0 < B_; b0 += CHUNK_B) {
        const long long qoff = (long long)b0 * H_ * N_ * HD_;
        const long long soff = (long long)b0 * H_ * N_ * N_;
        const int ZC = H_ * CHUNK_B;

        f16_gemm_nt<128, true><<<dim3(N_ / 128, N_ / 128, ZC), 128, SM128>>>(
            qh + qoff, kh + qoff, sS + soff, HD_, HD_, HD_, N_,
            (long long)N_ * HD_, (long long)N_ * HD_,
            (long long)H_ * N_ * N_, (long long)N_ * N_,
            scale, nullptr);

        softmax_mix_kernel<<<CHUNK_B * N_, 256>>>(
            sS + soff, pp + soff, rw, rb, gamma, beta, mean, var);

        f16_gemm_nt<96, true><<<dim3(1, N_ / 128, ZC), 128, SM96>>>(
            pp + soff, vt + qoff, ctx + (long long)b0 * N_ * DIM_,
            N_, N_, N_, DIM_,
            (long long)N_ * N_, (long long)HD_ * N_,
            (long long)N_ * DIM_, (long long)HD_,
            1.0f, nullptr);
    }

    // 6. projection + bias -> out fp32 (ctx likely L2-resident)
    f16_gemm_nt<128, false><<<dim3(DIM_ / 128, (B_ * N_) / 128, 1), 128, SM128>>>(
        ctx, wt, out, DIM_, DIM_, DIM_, DIM_,
        0LL, 0LL, 0LL, 0LL,
        1.0f, pb);
}

// round 13
// speedup vs baseline: 1.0750x; 1.0750x over previous
#include <cuda_runtime.h>
#include <cuda_fp16.h>
#include <math.h>
#include <stdint.h>

// Problem constants
#define B_   8
#define N_   1024
#define DIM_ 768
#define H_   8
#define HD_  96

// ---------------- scratch (device globals; no allocation allowed) ----------
__device__ __align__(256) __half g_qh[B_*H_*N_*HD_];   // (B,H,N,96) fp16
__device__ __align__(256) __half g_kh[B_*H_*N_*HD_];
__device__ __align__(256) __half g_vh[B_*H_*N_*HD_];
__device__ __align__(256) __half g_vt[B_*H_*HD_*N_];   // (B,H,96,N) fp16
__device__ __align__(256) __half g_wt[DIM_*DIM_];      // proj W^T [n][k] fp16
__device__ __align__(256) __half g_s[67108864];        // S logits (B,H,N,N) fp16
__device__ __align__(256) __half g_p[67108864];        // P (post softmax+mix) fp16
__device__ __align__(256) __half g_ctx[B_*N_*DIM_];    // (B,N,768) fp16

// ---------------------------------------------------------------------------
__device__ __forceinline__ void mma_f16(float* c, const uint32_t* a, const uint32_t* b) {
    asm volatile(
        "mma.sync.aligned.m16n8k16.row.col.f32.f16.f16.f32 "
        "{%0,%1,%2,%3}, {%4,%5,%6,%7}, {%8,%9}, {%0,%1,%2,%3};"
        : "+f"(c[0]), "+f"(c[1]), "+f"(c[2]), "+f"(c[3])
        : "r"(a[0]), "r"(a[1]), "r"(a[2]), "r"(a[3]), "r"(b[0]), "r"(b[1]));
}
__device__ __forceinline__ void ldm_x4(uint32_t* r, uint32_t saddr) {
    asm volatile("ldmatrix.sync.aligned.m8n8.x4.shared.b16 {%0,%1,%2,%3}, [%4];"
        : "=r"(r[0]), "=r"(r[1]), "=r"(r[2]), "=r"(r[3]) : "r"(saddr));
}
__device__ __forceinline__ void cp_async16(void* smem, const void* gmem) {
    uint32_t s = (uint32_t)__cvta_generic_to_shared(smem);
    asm volatile("cp.async.cg.shared.global [%0], [%1], 16;" :: "r"(s), "l"(gmem));
}
#define CP_COMMIT asm volatile("cp.async.commit_group;")
#define CP_WAIT1  asm volatile("cp.async.wait_group 1;")
#define CP_WAIT0  asm volatile("cp.async.wait_group 0;")

// ---------------------------------------------------------------------------
// Kernel 1: 3x3 SAME conv on 16x16x3 token image + head split -> fp16
// ---------------------------------------------------------------------------
__global__ void conv_heads_kernel(const float* __restrict__ q,
                                  const float* __restrict__ k,
                                  const float* __restrict__ v,
                                  const float* __restrict__ w) {
    __shared__ float img[768];
    __shared__ float wt[81];
    int token = blockIdx.x;
    int which = blockIdx.y;
    int tid = threadIdx.x;

    const float* src = (which == 0) ? q : (which == 1) ? k : v;
    __half* dst = (which == 0) ? g_qh : (which == 1) ? g_kh : g_vh;

    const float* xp = src + (size_t)token * DIM_;
    for (int i = tid; i < 768; i += 256) img[i] = xp[i];
    if (tid < 81) wt[tid] = w[tid];
    __syncthreads();

    int s = tid >> 4, t = tid & 15;
    float acc0 = 0.f, acc1 = 0.f, acc2 = 0.f;
#pragma unroll
    for (int dy = 0; dy < 3; ++dy) {
        int ys = s + dy - 1;
        bool vy = ((unsigned)ys < 16u);
#pragma unroll
        for (int dx = 0; dx < 3; ++dx) {
            int xs = t + dx - 1;
            if (vy && ((unsigned)xs < 16u)) {
                int base = (ys * 16 + xs) * 3;
                int wb = (dy * 3 + dx) * 9;
#pragma unroll
                for (int ci = 0; ci < 3; ++ci) {
                    float pv = img[base + ci];
                    acc0 += pv * wt[wb + ci * 3 + 0];
                    acc1 += pv * wt[wb + ci * 3 + 1];
                    acc2 += pv * wt[wb + ci * 3 + 2];
                }
            }
        }
    }
    int b = token >> 10, n = token & 1023;
    float accs[3] = {acc0, acc1, acc2};
    int p = tid * 3;
#pragma unroll
    for (int co = 0; co < 3; ++co) {
        int pp = p + co;
        int h = pp / 96;
        int d = pp - h * 96;
        dst[(((size_t)b * H_ + h) * N_ + n) * HD_ + d] = __float2half_rn(accs[co]);
    }
}

// ---------------------------------------------------------------------------
// Kernel 2: batched tiled transpose: (batch,R,C) -> (batch,C,R), TI -> half
// ---------------------------------------------------------------------------
template<typename TI>
__global__ void transpose_kernel(const TI* __restrict__ in, __half* __restrict__ out,
                                 int R, int C) {
    __shared__ float t[32][33];
    int c0 = blockIdx.x * 32, r0 = blockIdx.y * 32;
    const TI* ip = in + (size_t)blockIdx.z * R * C;
    __half* op = out + (size_t)blockIdx.z * R * C;
    int x = threadIdx.x, y = threadIdx.y;
#pragma unroll
    for (int i = 0; i < 32; i += 8)
        t[y + i][x] = (float)ip[(size_t)(r0 + y + i) * C + c0 + x];
    __syncthreads();
#pragma unroll
    for (int i = 0; i < 32; i += 8)
        op[(size_t)(c0 + y + i) * R + r0 + x] = __float2half_rn(t[x][y + i]);
}

// ---------------------------------------------------------------------------
// FP16 NT GEMM (fp32 accum), 4-stage cp.async ring, ONE barrier per k-tile,
// register fragment double-buffering, cp.async interleaved into compute.
// C[m][n] = scale * sum_k A[m][k]*Bt[n][k] (+ bias[n]).
// 128 threads = 4 warps (2x2). CTA tile 128 x BN, warp tile 64 x WN (WN=BN/2).
// BK=32 halves. Smem rows stride 20 uints (80B) -> conflict-free ldmatrix.
// ---------------------------------------------------------------------------
template<int BN, bool HALF_OUT>
__global__ __launch_bounds__(128, 2)
void f16_gemm_nt(const __half* __restrict__ A, const __half* __restrict__ Bt,
                 void* __restrict__ Cv,
                 int K, int lda, int ldb, int ldc,
                 long long sA, long long sB, long long sCo, long long sCi,
                 float scale, const float* __restrict__ bias) {
    constexpr int WN = BN / 2;
    constexpr int NF = WN / 8;              // 8 (BN=128) or 6 (BN=96)
    constexpr int ASTRIDE = 128 * 20;
    constexpr int BSTRIDE = BN * 20;
    extern __shared__ __align__(16) uint32_t smraw[];
    uint32_t* As0 = smraw;                  // 4 stages x 128*20
    uint32_t* Bs0 = smraw + 4 * ASTRIDE;    // 4 stages x BN*20

    int z = blockIdx.z;
    A += (size_t)z * sA;
    Bt += (size_t)z * sB;
    size_t coff = (size_t)(z >> 3) * sCo + (size_t)(z & 7) * sCi;

    int tid = threadIdx.x;
    int lane = tid & 31, w = tid >> 5;
    int wm = w >> 1, wn = w & 1;
    int gid = lane >> 2, tig = lane & 3;
    int m0 = blockIdx.y * 128, n0 = blockIdx.x * BN;

    // per-lane ldmatrix offsets (bytes within tile)
    int lt = lane >> 3, lr = lane & 7;
    int a_lane_off = ((lt & 1) * 8 + lr) * 80 + (lt >> 1) * 16;
    int b_lane_off = ((lt >> 1) * 8 + lr) * 80 + (lt & 1) * 16;

    float acc[4][NF][4];
#pragma unroll
    for (int i = 0; i < 4; ++i)
#pragma unroll
        for (int j = 0; j < NF; ++j)
#pragma unroll
            for (int r = 0; r < 4; ++r) acc[i][j][r] = 0.f;

    int T = K >> 5;   // BK = 32 halves

    auto load_tile = [&](int t, int stg) {
        int k0 = t * 32;
        uint32_t* Asg = As0 + stg * ASTRIDE;
        uint32_t* Bsg = Bs0 + stg * BSTRIDE;
#pragma unroll
        for (int it = 0; it < 4; ++it) {
            int idx = tid + it * 128;
            int row = idx >> 2, c = idx & 3;          // c: 16B chunk = 8 halves
            cp_async16(&Asg[row * 20 + c * 4],
                       &A[(size_t)(m0 + row) * lda + k0 + c * 8]);
        }
#pragma unroll
        for (int it = 0; it < (BN * 4 + 127) / 128; ++it) {
            int idx = tid + it * 128;
            if (BN == 128 || idx < BN * 4) {
                int row = idx >> 2, c = idx & 3;
                cp_async16(&Bsg[row * 20 + c * 4],
                           &Bt[(size_t)(n0 + row) * ldb + k0 + c * 8]);
            }
        }
    };

    load_tile(0, 0); CP_COMMIT;
    if (T > 1) { load_tile(1, 1); CP_COMMIT; }

    for (int t = 0; t < T; ++t) {
        if (t + 1 < T) { CP_WAIT1; }   // tile t resident (only t+1 may be pending)
        else { CP_WAIT0; }
        __syncthreads();

        int cur = t & 3;
        uint32_t abase = (uint32_t)__cvta_generic_to_shared(As0 + cur * ASTRIDE);
        uint32_t bbase = (uint32_t)__cvta_generic_to_shared(Bs0 + cur * BSTRIDE);

        uint32_t a[2][4][4];
        uint32_t bf[2][NF * 2];
        // k-group 0 fragments
#pragma unroll
        for (int i = 0; i < 4; ++i)
            ldm_x4(a[0][i], abase + (wm * 64 + i * 16) * 80 + a_lane_off);
#pragma unroll
        for (int p = 0; p < NF / 2; ++p)
            ldm_x4(&bf[0][p * 4], bbase + (wn * WN + p * 16) * 80 + b_lane_off);

        // prefetch tile t+2 into the ring while group-0 MMAs can proceed
        if (t + 2 < T) { load_tile(t + 2, (t + 2) & 3); CP_COMMIT; }

        // k-group 1 fragments (independent regs; issue behind group-0 MMAs)
#pragma unroll
        for (int i = 0; i < 4; ++i)
            ldm_x4(a[1][i], abase + (wm * 64 + i * 16) * 80 + 32 + a_lane_off);
#pragma unroll
        for (int p = 0; p < NF / 2; ++p)
            ldm_x4(&bf[1][p * 4], bbase + (wn * WN + p * 16) * 80 + 32 + b_lane_off);

#pragma unroll
        for (int g = 0; g < 2; ++g)
#pragma unroll
            for (int i = 0; i < 4; ++i)
#pragma unroll
                for (int j = 0; j < NF; ++j)
                    mma_f16(acc[i][j], a[g][i], &bf[g][j * 2]);
        // no trailing barrier (4-stage ring makes it safe)
    }

    // direct epilogue
#pragma unroll
    for (int i = 0; i < 4; ++i) {
        int r = m0 + wm * 64 + i * 16 + gid;
#pragma unroll
        for (int j = 0; j < NF; ++j) {
            int cgl = n0 + wn * WN + j * 8 + tig * 2;
            float x0 = acc[i][j][0] * scale, y0 = acc[i][j][1] * scale;
            float x1 = acc[i][j][2] * scale, y1 = acc[i][j][3] * scale;
            if (bias) {
                float bx = bias[cgl], by = bias[cgl + 1];
                x0 += bx; y0 += by; x1 += bx; y1 += by;
            }
            if (HALF_OUT) {
                __half* C = (__half*)Cv + coff;
                *(__half2*)&C[(size_t)r * ldc + cgl] = __floats2half2_rn(x0, y0);
                *(__half2*)&C[(size_t)(r + 8) * ldc + cgl] = __floats2half2_rn(x1, y1);
            } else {
                float* C = (float*)Cv + coff;
                *(float2*)&C[(size_t)r * ldc + cgl] = make_float2(x0, y0);
                *(float2*)&C[(size_t)(r + 8) * ldc + cgl] = make_float2(x1, y1);
            }
        }
    }
}

// ---------------------------------------------------------------------------
// Fused softmax + 8x8 head mix + BN. Register-resident per-warp softmax.
// One block (256 thr) per (b, n).
// ---------------------------------------------------------------------------
__global__ __launch_bounds__(256)
void softmax_mix_kernel(const __half* __restrict__ Sb, __half* __restrict__ Pb,
                        const float* __restrict__ rw, const float* __restrict__ rb,
                        const float* __restrict__ gamma, const float* __restrict__ beta,
                        const float* __restrict__ mean, const float* __restrict__ var) {
    __shared__ __half2 buf[8][512];
    __shared__ float Wm[8][8];
    __shared__ float Cm[8];
    int tid = threadIdx.x;
    int bn = blockIdx.x;
    int b = bn >> 10, n = bn & 1023;

    if (tid < 64) {
        int h = tid >> 3, g = tid & 7;
        float inv = gamma[g] * rsqrtf(var[g] + 1e-3f);
        Wm[h][g] = rw[h * 8 + g] * inv;
        if (h == 0) Cm[g] = (rb[g] - mean[g]) * inv + beta[g];
    }

    int w = tid >> 5, lane = tid & 31;
    size_t base = (size_t)b * 8388608 + (size_t)n * 1024;

    // load head w's row into registers: 4 uint4 = 16 half2 per lane
    const uint4* src = (const uint4*)(Sb + base + (size_t)w * 1048576);
    uint4 raw[4];
#pragma unroll
    for (int j = 0; j < 4; ++j) raw[j] = src[lane + j * 32];
    __half2* vh2 = (__half2*)raw;   // 16 half2, linear in m

    // max (fp16), reduce across warp
    __half2 m2 = vh2[0];
#pragma unroll
    for (int ii = 1; ii < 16; ++ii) m2 = __hmax2(m2, vh2[ii]);
#pragma unroll
    for (int o = 16; o > 0; o >>= 1) {
        uint32_t u = *(uint32_t*)&m2;
        u = __shfl_xor_sync(0xffffffffu, u, o);
        m2 = __hmax2(m2, *(__half2*)&u);
    }
    __half2 mx2 = __half2half2(__hmax(__low2half(m2), __high2half(m2)));
    const __half2 l2e = __float2half2_rn(1.44269504f);

    // exp in fp16 (ex2.f16x2), fp32 sum
    float s = 0.f;
#pragma unroll
    for (int ii = 0; ii < 16; ++ii) {
        __half2 e = h2exp2(__hmul2(__hsub2(vh2[ii], mx2), l2e));
        vh2[ii] = e;
        float2 f = __half22float2(e);
        s += f.x + f.y;
    }
#pragma unroll
    for (int o = 16; o > 0; o >>= 1) s += __shfl_xor_sync(0xffffffffu, s, o);
    __half2 inv2 = __float2half2_rn(1.0f / s);

    // normalize in fp16 (P is fp16 downstream anyway), store to smem
#pragma unroll
    for (int ii = 0; ii < 16; ++ii) vh2[ii] = __hmul2(vh2[ii], inv2);
    uint4* brow = (uint4*)&buf[w][0];
#pragma unroll
    for (int j = 0; j < 4; ++j) brow[lane + j * 32] = raw[j];
    __syncthreads();

    // mix heads in fp32, 4 columns (m = 4*tid..4*tid+3) per thread
    float4 p[8];
#pragma unroll
    for (int h = 0; h < 8; ++h) {
        float2 rawm = ((const float2*)&buf[h][0])[tid];   // 2 half2 = 4 halves
        __half2 lo = *(__half2*)&rawm.x, hi = *(__half2*)&rawm.y;
        float2 f0 = __half22float2(lo), f1 = __half22float2(hi);
        p[h] = make_float4(f0.x, f0.y, f1.x, f1.y);
    }
    float2* gout = (float2*)(Pb + base);                // 8B = 4 halves
#pragma unroll
    for (int g = 0; g < 8; ++g) {
        float c = Cm[g];
        float4 o = make_float4(c, c, c, c);
#pragma unroll
        for (int h = 0; h < 8; ++h) {
            float wv = Wm[h][g];
            o.x += p[h].x * wv; o.y += p[h].y * wv;
            o.z += p[h].z * wv; o.w += p[h].w * wv;
        }
        float2 st;
        *(__half2*)&st.x = __floats2half2_rn(o.x, o.y);
        *(__half2*)&st.y = __floats2half2_rn(o.z, o.w);
        gout[(size_t)g * 262144 + tid] = st;
    }
}

// ---------------------------------------------------------------------------
extern "C" void kernel_launch(void* const* d_in, const int* in_sizes, int n_in,
                              void* d_out, int out_size) {
    const float* q      = (const float*)d_in[0];
    const float* k      = (const float*)d_in[1];
    const float* v      = (const float*)d_in[2];
    const float* conv_w = (const float*)d_in[3];
    const float* rw     = (const float*)d_in[4];
    const float* rb     = (const float*)d_in[5];
    const float* gamma  = (const float*)d_in[6];
    const float* beta   = (const float*)d_in[7];
    const float* mean   = (const float*)d_in[8];
    const float* var    = (const float*)d_in[9];
    const float* pw     = (const float*)d_in[10];
    const float* pb     = (const float*)d_in[11];
    float* out = (float*)d_out;

    float scale = 1.0f / sqrtf((float)HD_);

    __half *qh, *kh, *vh, *vt, *wt, *sS, *pp, *ctx;
    cudaGetSymbolAddress((void**)&qh, g_qh);
    cudaGetSymbolAddress((void**)&kh, g_kh);
    cudaGetSymbolAddress((void**)&vh, g_vh);
    cudaGetSymbolAddress((void**)&vt, g_vt);
    cudaGetSymbolAddress((void**)&wt, g_wt);
    cudaGetSymbolAddress((void**)&sS, g_s);
    cudaGetSymbolAddress((void**)&pp, g_p);
    cudaGetSymbolAddress((void**)&ctx, g_ctx);

    const int SM128 = 4 * (128 + 128) * 20 * 4;   // 81920 B
    const int SM96  = 4 * (128 + 96) * 20 * 4;    // 71680 B
    cudaFuncSetAttribute(f16_gemm_nt<128, true>,
                         cudaFuncAttributeMaxDynamicSharedMemorySize, SM128);
    cudaFuncSetAttribute(f16_gemm_nt<96, true>,
                         cudaFuncAttributeMaxDynamicSharedMemorySize, SM96);
    cudaFuncSetAttribute(f16_gemm_nt<128, false>,
                         cudaFuncAttributeMaxDynamicSharedMemorySize, SM128);

    // 1. conv + head split (fp16 outputs)
    conv_heads_kernel<<<dim3(B_ * N_, 3), 256>>>(q, k, v, conv_w);

    // 2. transposes: V(half) -> (B,H,96,N) half, W(float) -> [n][k] half
    transpose_kernel<__half><<<dim3(HD_ / 32, N_ / 32, B_ * H_), dim3(32, 8)>>>(vh, vt, N_, HD_);
    transpose_kernel<float><<<dim3(DIM_ / 32, DIM_ / 32, 1), dim3(32, 8)>>>(pw, wt, DIM_, DIM_);

    // 3. QK^T (scaled) -> S fp16
    f16_gemm_nt<128, true><<<dim3(N_ / 128, N_ / 128, B_ * H_), 128, SM128>>>(
        qh, kh, sS, HD_, HD_, HD_, N_,
        (long long)N_ * HD_, (long long)N_ * HD_,
        (long long)H_ * N_ * N_, (long long)N_ * N_,
        scale, nullptr);

    // 4. softmax + head mix + BN -> P fp16
    softmax_mix_kernel<<<B_ * N_, 256>>>(sS, pp, rw, rb, gamma, beta, mean, var);

    // 5. AV -> ctx (B,N,768) fp16
    f16_gemm_nt<96, true><<<dim3(1, N_ / 128, B_ * H_), 128, SM96>>>(
        pp, vt, ctx, N_, N_, N_, DIM_,
        (long long)N_ * N_, (long long)HD_ * N_,
        (long long)N_ * DIM_, (long long)HD_,
        1.0f, nullptr);

    // 6. projection + bias -> out fp32
    f16_gemm_nt<128, false><<<dim3(DIM_ / 128, (B_ * N_) / 128, 1), 128, SM128>>>(
        ctx, wt, out, DIM_, DIM_, DIM_, DIM_,
        0LL, 0LL, 0LL, 0LL,
        1.0f, pb);
}

// round 14
// speedup vs baseline: 1.0969x; 1.0203x over previous
#include <cuda_runtime.h>
#include <cuda_fp16.h>
#include <math.h>
#include <stdint.h>

// Problem constants
#define B_   8
#define N_   1024
#define DIM_ 768
#define H_   8
#define HD_  96

// ---------------- scratch (device globals; no allocation allowed) ----------
__device__ __align__(256) __half g_qh[B_*H_*N_*HD_];   // (B,H,N,96) fp16
__device__ __align__(256) __half g_kh[B_*H_*N_*HD_];
__device__ __align__(256) __half g_vh[B_*H_*N_*HD_];
__device__ __align__(256) __half g_vt[B_*H_*HD_*N_];   // (B,H,96,N) fp16
__device__ __align__(256) __half g_wt[DIM_*DIM_];      // proj W^T [n][k] fp16
__device__ __align__(256) __half g_s[67108864];        // S logits (B,H,N,N) fp16
__device__ __align__(256) __half g_p[67108864];        // P (post softmax+mix) fp16
__device__ __align__(256) __half g_ctx[B_*N_*DIM_];    // (B,N,768) fp16

// ---------------------------------------------------------------------------
__device__ __forceinline__ void mma_f16(float* c, const uint32_t* a, const uint32_t* b) {
    asm volatile(
        "mma.sync.aligned.m16n8k16.row.col.f32.f16.f16.f32 "
        "{%0,%1,%2,%3}, {%4,%5,%6,%7}, {%8,%9}, {%0,%1,%2,%3};"
        : "+f"(c[0]), "+f"(c[1]), "+f"(c[2]), "+f"(c[3])
        : "r"(a[0]), "r"(a[1]), "r"(a[2]), "r"(a[3]), "r"(b[0]), "r"(b[1]));
}
__device__ __forceinline__ void ldm_x4(uint32_t* r, uint32_t saddr) {
    asm volatile("ldmatrix.sync.aligned.m8n8.x4.shared.b16 {%0,%1,%2,%3}, [%4];"
        : "=r"(r[0]), "=r"(r[1]), "=r"(r[2]), "=r"(r[3]) : "r"(saddr));
}
__device__ __forceinline__ void cp_async16(void* smem, const void* gmem) {
    uint32_t s = (uint32_t)__cvta_generic_to_shared(smem);
    asm volatile("cp.async.cg.shared.global [%0], [%1], 16;" :: "r"(s), "l"(gmem));
}
#define CP_COMMIT asm volatile("cp.async.commit_group;")
#define CP_WAIT2  asm volatile("cp.async.wait_group 2;")
#define CP_WAIT1  asm volatile("cp.async.wait_group 1;")
#define CP_WAIT0  asm volatile("cp.async.wait_group 0;")

// ---------------------------------------------------------------------------
// Kernel 1: 3x3 SAME conv on 16x16x3 token image + head split -> fp16
// ---------------------------------------------------------------------------
__global__ void conv_heads_kernel(const float* __restrict__ q,
                                  const float* __restrict__ k,
                                  const float* __restrict__ v,
                                  const float* __restrict__ w) {
    __shared__ float img[768];
    __shared__ float wt[81];
    int token = blockIdx.x;
    int which = blockIdx.y;
    int tid = threadIdx.x;

    const float* src = (which == 0) ? q : (which == 1) ? k : v;
    __half* dst = (which == 0) ? g_qh : (which == 1) ? g_kh : g_vh;

    const float* xp = src + (size_t)token * DIM_;
    for (int i = tid; i < 768; i += 256) img[i] = xp[i];
    if (tid < 81) wt[tid] = w[tid];
    __syncthreads();

    int s = tid >> 4, t = tid & 15;
    float acc0 = 0.f, acc1 = 0.f, acc2 = 0.f;
#pragma unroll
    for (int dy = 0; dy < 3; ++dy) {
        int ys = s + dy - 1;
        bool vy = ((unsigned)ys < 16u);
#pragma unroll
        for (int dx = 0; dx < 3; ++dx) {
            int xs = t + dx - 1;
            if (vy && ((unsigned)xs < 16u)) {
                int base = (ys * 16 + xs) * 3;
                int wb = (dy * 3 + dx) * 9;
#pragma unroll
                for (int ci = 0; ci < 3; ++ci) {
                    float pv = img[base + ci];
                    acc0 += pv * wt[wb + ci * 3 + 0];
                    acc1 += pv * wt[wb + ci * 3 + 1];
                    acc2 += pv * wt[wb + ci * 3 + 2];
                }
            }
        }
    }
    int b = token >> 10, n = token & 1023;
    float accs[3] = {acc0, acc1, acc2};
    int p = tid * 3;
#pragma unroll
    for (int co = 0; co < 3; ++co) {
        int pp = p + co;
        int h = pp / 96;
        int d = pp - h * 96;
        dst[(((size_t)b * H_ + h) * N_ + n) * HD_ + d] = __float2half_rn(accs[co]);
    }
}

// ---------------------------------------------------------------------------
// Kernel 2: batched tiled transpose: (batch,R,C) -> (batch,C,R), TI -> half
// ---------------------------------------------------------------------------
template<typename TI>
__global__ void transpose_kernel(const TI* __restrict__ in, __half* __restrict__ out,
                                 int R, int C) {
    __shared__ float t[32][33];
    int c0 = blockIdx.x * 32, r0 = blockIdx.y * 32;
    const TI* ip = in + (size_t)blockIdx.z * R * C;
    __half* op = out + (size_t)blockIdx.z * R * C;
    int x = threadIdx.x, y = threadIdx.y;
#pragma unroll
    for (int i = 0; i < 32; i += 8)
        t[y + i][x] = (float)ip[(size_t)(r0 + y + i) * C + c0 + x];
    __syncthreads();
#pragma unroll
    for (int i = 0; i < 32; i += 8)
        op[(size_t)(c0 + y + i) * R + r0 + x] = __float2half_rn(t[x][y + i]);
}

// ---------------------------------------------------------------------------
// FP16 NT GEMM (fp32 accum), 4-stage cp.async ring, ONE barrier per k-tile.
// C[m][n] = scale * sum_k A[m][k]*Bt[n][k] (+ bias[n]).
// 128 threads = 4 warps (2x2). CTA tile 128 x BN, warp tile 64 x WN (WN=BN/2).
// BK=32 halves. Smem rows stride 20 uints (80B) -> conflict-free ldmatrix.
// (round-11 mainloop, proven fastest; BN in {128, 96, 64}, NF even)
// ---------------------------------------------------------------------------
template<int BN, bool HALF_OUT>
__global__ __launch_bounds__(128, 2)
void f16_gemm_nt(const __half* __restrict__ A, const __half* __restrict__ Bt,
                 void* __restrict__ Cv,
                 int K, int lda, int ldb, int ldc,
                 long long sA, long long sB, long long sCo, long long sCi,
                 float scale, const float* __restrict__ bias) {
    constexpr int WN = BN / 2;
    constexpr int NF = WN / 8;              // 8 / 6 / 4
    constexpr int ASTRIDE = 128 * 20;
    constexpr int BSTRIDE = BN * 20;
    extern __shared__ __align__(16) uint32_t smraw[];
    uint32_t* As0 = smraw;                  // 4 stages x 128*20
    uint32_t* Bs0 = smraw + 4 * ASTRIDE;    // 4 stages x BN*20

    int z = blockIdx.z;
    A += (size_t)z * sA;
    Bt += (size_t)z * sB;
    size_t coff = (size_t)(z >> 3) * sCo + (size_t)(z & 7) * sCi;

    int tid = threadIdx.x;
    int lane = tid & 31, w = tid >> 5;
    int wm = w >> 1, wn = w & 1;
    int gid = lane >> 2, tig = lane & 3;
    int m0 = blockIdx.y * 128, n0 = blockIdx.x * BN;

    // per-lane ldmatrix offsets (bytes within tile)
    int lt = lane >> 3, lr = lane & 7;
    int a_lane_off = ((lt & 1) * 8 + lr) * 80 + (lt >> 1) * 16;
    int b_lane_off = ((lt >> 1) * 8 + lr) * 80 + (lt & 1) * 16;

    float acc[4][NF][4];
#pragma unroll
    for (int i = 0; i < 4; ++i)
#pragma unroll
        for (int j = 0; j < NF; ++j)
#pragma unroll
            for (int r = 0; r < 4; ++r) acc[i][j][r] = 0.f;

    int T = K >> 5;   // BK = 32 halves

    auto load_tile = [&](int t, int stg) {
        int k0 = t * 32;
        uint32_t* Asg = As0 + stg * ASTRIDE;
        uint32_t* Bsg = Bs0 + stg * BSTRIDE;
#pragma unroll
        for (int it = 0; it < 4; ++it) {
            int idx = tid + it * 128;
            int row = idx >> 2, c = idx & 3;          // c: 16B chunk = 8 halves
            cp_async16(&Asg[row * 20 + c * 4],
                       &A[(size_t)(m0 + row) * lda + k0 + c * 8]);
        }
#pragma unroll
        for (int it = 0; it < (BN * 4 + 127) / 128; ++it) {
            int idx = tid + it * 128;
            if ((BN & 31) == 0 || idx < BN * 4) {
                int row = idx >> 2, c = idx & 3;
                cp_async16(&Bsg[row * 20 + c * 4],
                           &Bt[(size_t)(n0 + row) * ldb + k0 + c * 8]);
            }
        }
    };

    load_tile(0, 0); CP_COMMIT;
    if (T > 1) { load_tile(1, 1); CP_COMMIT; }

    for (int t = 0; t < T; ++t) {
        if (t + 2 < T) { load_tile(t + 2, (t + 2) & 3); CP_COMMIT; CP_WAIT2; }
        else if (t + 1 < T) { CP_WAIT1; }
        else { CP_WAIT0; }
        __syncthreads();

        int cur = t & 3;
        uint32_t abase = (uint32_t)__cvta_generic_to_shared(As0 + cur * ASTRIDE);
        uint32_t bbase = (uint32_t)__cvta_generic_to_shared(Bs0 + cur * BSTRIDE);
#pragma unroll
        for (int kk = 0; kk < 16; kk += 8) {   // 2 k-groups of 16 halves
            int kk4 = kk * 4;
            uint32_t a[4][4];
#pragma unroll
            for (int i = 0; i < 4; ++i)
                ldm_x4(a[i], abase + (wm * 64 + i * 16) * 80 + kk4 + a_lane_off);
            uint32_t bf[NF * 2];
#pragma unroll
            for (int p = 0; p < NF / 2; ++p)
                ldm_x4(&bf[p * 4], bbase + (wn * WN + p * 16) * 80 + kk4 + b_lane_off);
#pragma unroll
            for (int i = 0; i < 4; ++i)
#pragma unroll
                for (int j = 0; j < NF; ++j)
                    mma_f16(acc[i][j], a[i], &bf[j * 2]);
        }
        // no trailing barrier (4-stage ring makes it safe)
    }

    // direct epilogue
#pragma unroll
    for (int i = 0; i < 4; ++i) {
        int r = m0 + wm * 64 + i * 16 + gid;
#pragma unroll
        for (int j = 0; j < NF; ++j) {
            int cgl = n0 + wn * WN + j * 8 + tig * 2;
            float x0 = acc[i][j][0] * scale, y0 = acc[i][j][1] * scale;
            float x1 = acc[i][j][2] * scale, y1 = acc[i][j][3] * scale;
            if (bias) {
                float bx = bias[cgl], by = bias[cgl + 1];
                x0 += bx; y0 += by; x1 += bx; y1 += by;
            }
            if (HALF_OUT) {
                __half* C = (__half*)Cv + coff;
                *(__half2*)&C[(size_t)r * ldc + cgl] = __floats2half2_rn(x0, y0);
                *(__half2*)&C[(size_t)(r + 8) * ldc + cgl] = __floats2half2_rn(x1, y1);
            } else {
                float* C = (float*)Cv + coff;
                *(float2*)&C[(size_t)r * ldc + cgl] = make_float2(x0, y0);
                *(float2*)&C[(size_t)(r + 8) * ldc + cgl] = make_float2(x1, y1);
            }
        }
    }
}

// ---------------------------------------------------------------------------
// Fused softmax + 8x8 head mix + BN. Register-resident per-warp softmax.
// One block (256 thr) per (b, n).
// ---------------------------------------------------------------------------
__global__ __launch_bounds__(256)
void softmax_mix_kernel(const __half* __restrict__ Sb, __half* __restrict__ Pb,
                        const float* __restrict__ rw, const float* __restrict__ rb,
                        const float* __restrict__ gamma, const float* __restrict__ beta,
                        const float* __restrict__ mean, const float* __restrict__ var) {
    __shared__ __half2 buf[8][512];
    __shared__ float Wm[8][8];
    __shared__ float Cm[8];
    int tid = threadIdx.x;
    int bn = blockIdx.x;
    int b = bn >> 10, n = bn & 1023;

    if (tid < 64) {
        int h = tid >> 3, g = tid & 7;
        float inv = gamma[g] * rsqrtf(var[g] + 1e-3f);
        Wm[h][g] = rw[h * 8 + g] * inv;
        if (h == 0) Cm[g] = (rb[g] - mean[g]) * inv + beta[g];
    }

    int w = tid >> 5, lane = tid & 31;
    size_t base = (size_t)b * 8388608 + (size_t)n * 1024;

    // load head w's row into registers: 4 uint4 = 16 half2 per lane
    const uint4* src = (const uint4*)(Sb + base + (size_t)w * 1048576);
    uint4 raw[4];
#pragma unroll
    for (int j = 0; j < 4; ++j) raw[j] = src[lane + j * 32];
    __half2* vh2 = (__half2*)raw;   // 16 half2, linear in m

    // max (fp16), reduce across warp
    __half2 m2 = vh2[0];
#pragma unroll
    for (int ii = 1; ii < 16; ++ii) m2 = __hmax2(m2, vh2[ii]);
#pragma unroll
    for (int o = 16; o > 0; o >>= 1) {
        uint32_t u = *(uint32_t*)&m2;
        u = __shfl_xor_sync(0xffffffffu, u, o);
        m2 = __hmax2(m2, *(__half2*)&u);
    }
    __half2 mx2 = __half2half2(__hmax(__low2half(m2), __high2half(m2)));
    const __half2 l2e = __float2half2_rn(1.44269504f);

    // exp in fp16 (ex2.f16x2), fp32 sum
    float s = 0.f;
#pragma unroll
    for (int ii = 0; ii < 16; ++ii) {
        __half2 e = h2exp2(__hmul2(__hsub2(vh2[ii], mx2), l2e));
        vh2[ii] = e;
        float2 f = __half22float2(e);
        s += f.x + f.y;
    }
#pragma unroll
    for (int o = 16; o > 0; o >>= 1) s += __shfl_xor_sync(0xffffffffu, s, o);
    __half2 inv2 = __float2half2_rn(1.0f / s);

    // normalize in fp16 (P is fp16 downstream anyway), store to smem
#pragma unroll
    for (int ii = 0; ii < 16; ++ii) vh2[ii] = __hmul2(vh2[ii], inv2);
    uint4* brow = (uint4*)&buf[w][0];
#pragma unroll
    for (int j = 0; j < 4; ++j) brow[lane + j * 32] = raw[j];
    __syncthreads();

    // mix heads in fp32, 4 columns (m = 4*tid..4*tid+3) per thread
    float4 p[8];
#pragma unroll
    for (int h = 0; h < 8; ++h) {
        float2 rawm = ((const float2*)&buf[h][0])[tid];   // 2 half2 = 4 halves
        __half2 lo = *(__half2*)&rawm.x, hi = *(__half2*)&rawm.y;
        float2 f0 = __half22float2(lo), f1 = __half22float2(hi);
        p[h] = make_float4(f0.x, f0.y, f1.x, f1.y);
    }
    float2* gout = (float2*)(Pb + base);                // 8B = 4 halves
#pragma unroll
    for (int g = 0; g < 8; ++g) {
        float c = Cm[g];
        float4 o = make_float4(c, c, c, c);
#pragma unroll
        for (int h = 0; h < 8; ++h) {
            float wv = Wm[h][g];
            o.x += p[h].x * wv; o.y += p[h].y * wv;
            o.z += p[h].z * wv; o.w += p[h].w * wv;
        }
        float2 st;
        *(__half2*)&st.x = __floats2half2_rn(o.x, o.y);
        *(__half2*)&st.y = __floats2half2_rn(o.z, o.w);
        gout[(size_t)g * 262144 + tid] = st;
    }
}

// ---------------------------------------------------------------------------
extern "C" void kernel_launch(void* const* d_in, const int* in_sizes, int n_in,
                              void* d_out, int out_size) {
    const float* q      = (const float*)d_in[0];
    const float* k      = (const float*)d_in[1];
    const float* v      = (const float*)d_in[2];
    const float* conv_w = (const float*)d_in[3];
    const float* rw     = (const float*)d_in[4];
    const float* rb     = (const float*)d_in[5];
    const float* gamma  = (const float*)d_in[6];
    const float* beta   = (const float*)d_in[7];
    const float* mean   = (const float*)d_in[8];
    const float* var    = (const float*)d_in[9];
    const float* pw     = (const float*)d_in[10];
    const float* pb     = (const float*)d_in[11];
    float* out = (float*)d_out;

    float scale = 1.0f / sqrtf((float)HD_);

    __half *qh, *kh, *vh, *vt, *wt, *sS, *pp, *ctx;
    cudaGetSymbolAddress((void**)&qh, g_qh);
    cudaGetSymbolAddress((void**)&kh, g_kh);
    cudaGetSymbolAddress((void**)&vh, g_vh);
    cudaGetSymbolAddress((void**)&vt, g_vt);
    cudaGetSymbolAddress((void**)&wt, g_wt);
    cudaGetSymbolAddress((void**)&sS, g_s);
    cudaGetSymbolAddress((void**)&pp, g_p);
    cudaGetSymbolAddress((void**)&ctx, g_ctx);

    const int SM128 = 4 * (128 + 128) * 20 * 4;   // 81920 B
    const int SM96  = 4 * (128 + 96) * 20 * 4;    // 71680 B
    const int SM64  = 4 * (128 + 64) * 20 * 4;    // 61440 B
    cudaFuncSetAttribute(f16_gemm_nt<128, true>,
                         cudaFuncAttributeMaxDynamicSharedMemorySize, SM128);
    cudaFuncSetAttribute(f16_gemm_nt<96, true>,
                         cudaFuncAttributeMaxDynamicSharedMemorySize, SM96);
    cudaFuncSetAttribute(f16_gemm_nt<64, false>,
                         cudaFuncAttributeMaxDynamicSharedMemorySize, SM64);

    // 1. conv + head split (fp16 outputs)
    conv_heads_kernel<<<dim3(B_ * N_, 3), 256>>>(q, k, v, conv_w);

    // 2. transposes: V(half) -> (B,H,96,N) half, W(float) -> [n][k] half
    transpose_kernel<__half><<<dim3(HD_ / 32, N_ / 32, B_ * H_), dim3(32, 8)>>>(vh, vt, N_, HD_);
    transpose_kernel<float><<<dim3(DIM_ / 32, DIM_ / 32, 1), dim3(32, 8)>>>(pw, wt, DIM_, DIM_);

    // 3. QK^T (scaled) -> S fp16
    f16_gemm_nt<128, true><<<dim3(N_ / 128, N_ / 128, B_ * H_), 128, SM128>>>(
        qh, kh, sS, HD_, HD_, HD_, N_,
        (long long)N_ * HD_, (long long)N_ * HD_,
        (long long)H_ * N_ * N_, (long long)N_ * N_,
        scale, nullptr);

    // 4. softmax + head mix + BN -> P fp16
    softmax_mix_kernel<<<B_ * N_, 256>>>(sS, pp, rw, rb, gamma, beta, mean, var);

    // 5. AV -> ctx (B,N,768) fp16
    f16_gemm_nt<96, true><<<dim3(1, N_ / 128, B_ * H_), 128, SM96>>>(
        pp, vt, ctx, N_, N_, N_, DIM_,
        (long long)N_ * N_, (long long)HD_ * N_,
        (long long)N_ * DIM_, (long long)HD_,
        1.0f, nullptr);

    // 6. projection + bias -> out fp32 (BN=64: 768 tiles -> 3 waves @ 1.16x
    //    quantization instead of 384 tiles -> 2 waves @ 1.54x)
    f16_gemm_nt<64, false><<<dim3(DIM_ / 64, (B_ * N_) / 128, 1), 128, SM64>>>(
        ctx, wt, out, DIM_, DIM_, DIM_, DIM_,
        0LL, 0LL, 0LL, 0LL,
        1.0f, pb);
}

// round 15
// speedup vs baseline: 1.1217x; 1.0227x over previous
#include <cuda_runtime.h>
#include <cuda_fp16.h>
#include <math.h>
#include <stdint.h>

// Problem constants
#define B_   8
#define N_   1024
#define DIM_ 768
#define H_   8
#define HD_  96

// ---------------- scratch (device globals; no allocation allowed) ----------
__device__ __align__(256) __half g_qh[B_*H_*N_*HD_];   // (B,H,N,96) fp16
__device__ __align__(256) __half g_kh[B_*H_*N_*HD_];
__device__ __align__(256) __half g_vh[B_*H_*N_*HD_];
__device__ __align__(256) __half g_vt[B_*H_*HD_*N_];   // (B,H,96,N) fp16
__device__ __align__(256) __half g_wt[DIM_*DIM_];      // proj W^T [n][k] fp16
__device__ __align__(256) __half g_s[67108864];        // S logits (B,H,N,N) fp16
__device__ __align__(256) __half g_p[67108864];        // P (post softmax+mix) fp16
__device__ __align__(256) __half g_ctx[B_*N_*DIM_];    // (B,N,768) fp16

// ---------------------------------------------------------------------------
__device__ __forceinline__ void mma_f16(float* c, const uint32_t* a, const uint32_t* b) {
    asm volatile(
        "mma.sync.aligned.m16n8k16.row.col.f32.f16.f16.f32 "
        "{%0,%1,%2,%3}, {%4,%5,%6,%7}, {%8,%9}, {%0,%1,%2,%3};"
        : "+f"(c[0]), "+f"(c[1]), "+f"(c[2]), "+f"(c[3])
        : "r"(a[0]), "r"(a[1]), "r"(a[2]), "r"(a[3]), "r"(b[0]), "r"(b[1]));
}
__device__ __forceinline__ void ldm_x4(uint32_t* r, uint32_t saddr) {
    asm volatile("ldmatrix.sync.aligned.m8n8.x4.shared.b16 {%0,%1,%2,%3}, [%4];"
        : "=r"(r[0]), "=r"(r[1]), "=r"(r[2]), "=r"(r[3]) : "r"(saddr));
}
__device__ __forceinline__ void cp_async16(void* smem, const void* gmem) {
    uint32_t s = (uint32_t)__cvta_generic_to_shared(smem);
    asm volatile("cp.async.cg.shared.global [%0], [%1], 16;" :: "r"(s), "l"(gmem));
}
#define CP_COMMIT asm volatile("cp.async.commit_group;")
#define CP_WAIT2  asm volatile("cp.async.wait_group 2;")
#define CP_WAIT1  asm volatile("cp.async.wait_group 1;")
#define CP_WAIT0  asm volatile("cp.async.wait_group 0;")

// ---------------------------------------------------------------------------
// Kernel 1: 3x3 SAME conv on 16x16x3 token image + head split -> fp16
// ---------------------------------------------------------------------------
__global__ void conv_heads_kernel(const float* __restrict__ q,
                                  const float* __restrict__ k,
                                  const float* __restrict__ v,
                                  const float* __restrict__ w) {
    __shared__ float img[768];
    __shared__ float wt[81];
    int token = blockIdx.x;
    int which = blockIdx.y;
    int tid = threadIdx.x;

    const float* src = (which == 0) ? q : (which == 1) ? k : v;
    __half* dst = (which == 0) ? g_qh : (which == 1) ? g_kh : g_vh;

    const float* xp = src + (size_t)token * DIM_;
    for (int i = tid; i < 768; i += 256) img[i] = xp[i];
    if (tid < 81) wt[tid] = w[tid];
    __syncthreads();

    int s = tid >> 4, t = tid & 15;
    float acc0 = 0.f, acc1 = 0.f, acc2 = 0.f;
#pragma unroll
    for (int dy = 0; dy < 3; ++dy) {
        int ys = s + dy - 1;
        bool vy = ((unsigned)ys < 16u);
#pragma unroll
        for (int dx = 0; dx < 3; ++dx) {
            int xs = t + dx - 1;
            if (vy && ((unsigned)xs < 16u)) {
                int base = (ys * 16 + xs) * 3;
                int wb = (dy * 3 + dx) * 9;
#pragma unroll
                for (int ci = 0; ci < 3; ++ci) {
                    float pv = img[base + ci];
                    acc0 += pv * wt[wb + ci * 3 + 0];
                    acc1 += pv * wt[wb + ci * 3 + 1];
                    acc2 += pv * wt[wb + ci * 3 + 2];
                }
            }
        }
    }
    int b = token >> 10, n = token & 1023;
    float accs[3] = {acc0, acc1, acc2};
    int p = tid * 3;
#pragma unroll
    for (int co = 0; co < 3; ++co) {
        int pp = p + co;
        int h = pp / 96;
        int d = pp - h * 96;
        dst[(((size_t)b * H_ + h) * N_ + n) * HD_ + d] = __float2half_rn(accs[co]);
    }
}

// ---------------------------------------------------------------------------
// Kernel 2: batched tiled transpose: (batch,R,C) -> (batch,C,R), TI -> half
// ---------------------------------------------------------------------------
template<typename TI>
__global__ void transpose_kernel(const TI* __restrict__ in, __half* __restrict__ out,
                                 int R, int C) {
    __shared__ float t[32][33];
    int c0 = blockIdx.x * 32, r0 = blockIdx.y * 32;
    const TI* ip = in + (size_t)blockIdx.z * R * C;
    __half* op = out + (size_t)blockIdx.z * R * C;
    int x = threadIdx.x, y = threadIdx.y;
#pragma unroll
    for (int i = 0; i < 32; i += 8)
        t[y + i][x] = (float)ip[(size_t)(r0 + y + i) * C + c0 + x];
    __syncthreads();
#pragma unroll
    for (int i = 0; i < 32; i += 8)
        op[(size_t)(c0 + y + i) * R + r0 + x] = __float2half_rn(t[x][y + i]);
}

// ---------------------------------------------------------------------------
// FP16 NT GEMM (fp32 accum), 4-stage cp.async ring, ONE barrier per k-tile.
// C[m][n] = scale * sum_k A[m][k]*Bt[n][k] (+ bias[n]).
// 128 threads = 4 warps (2x2). CTA tile BM x BN, warp tile (BM/2) x (BN/2).
// BK=32 halves. Smem rows stride 20 uints (80B) -> conflict-free ldmatrix.
// (round-11 mainloop; BM in {128,64}, BN in {128,96})
// ---------------------------------------------------------------------------
template<int BM, int BN, bool HALF_OUT>
__global__ __launch_bounds__(128, 2)
void f16_gemm_nt(const __half* __restrict__ A, const __half* __restrict__ Bt,
                 void* __restrict__ Cv,
                 int K, int lda, int ldb, int ldc,
                 long long sA, long long sB, long long sCo, long long sCi,
                 float scale, const float* __restrict__ bias) {
    constexpr int WN = BN / 2;
    constexpr int NF = WN / 8;              // 8 / 6 / 4
    constexpr int MF = BM / 32;             // M-frags per warp (4 or 2)
    constexpr int ASTRIDE = BM * 20;
    constexpr int BSTRIDE = BN * 20;
    extern __shared__ __align__(16) uint32_t smraw[];
    uint32_t* As0 = smraw;                  // 4 stages x BM*20
    uint32_t* Bs0 = smraw + 4 * ASTRIDE;    // 4 stages x BN*20

    int z = blockIdx.z;
    A += (size_t)z * sA;
    Bt += (size_t)z * sB;
    size_t coff = (size_t)(z >> 3) * sCo + (size_t)(z & 7) * sCi;

    int tid = threadIdx.x;
    int lane = tid & 31, w = tid >> 5;
    int wm = w >> 1, wn = w & 1;
    int gid = lane >> 2, tig = lane & 3;
    int m0 = blockIdx.y * BM, n0 = blockIdx.x * BN;

    // per-lane ldmatrix offsets (bytes within tile)
    int lt = lane >> 3, lr = lane & 7;
    int a_lane_off = ((lt & 1) * 8 + lr) * 80 + (lt >> 1) * 16;
    int b_lane_off = ((lt >> 1) * 8 + lr) * 80 + (lt & 1) * 16;

    float acc[MF][NF][4];
#pragma unroll
    for (int i = 0; i < MF; ++i)
#pragma unroll
        for (int j = 0; j < NF; ++j)
#pragma unroll
            for (int r = 0; r < 4; ++r) acc[i][j][r] = 0.f;

    int T = K >> 5;   // BK = 32 halves

    auto load_tile = [&](int t, int stg) {
        int k0 = t * 32;
        uint32_t* Asg = As0 + stg * ASTRIDE;
        uint32_t* Bsg = Bs0 + stg * BSTRIDE;
#pragma unroll
        for (int it = 0; it < BM / 32; ++it) {
            int idx = tid + it * 128;
            int row = idx >> 2, c = idx & 3;          // c: 16B chunk = 8 halves
            cp_async16(&Asg[row * 20 + c * 4],
                       &A[(size_t)(m0 + row) * lda + k0 + c * 8]);
        }
#pragma unroll
        for (int it = 0; it < (BN * 4 + 127) / 128; ++it) {
            int idx = tid + it * 128;
            if ((BN & 31) == 0 || idx < BN * 4) {
                int row = idx >> 2, c = idx & 3;
                cp_async16(&Bsg[row * 20 + c * 4],
                           &Bt[(size_t)(n0 + row) * ldb + k0 + c * 8]);
            }
        }
    };

    load_tile(0, 0); CP_COMMIT;
    if (T > 1) { load_tile(1, 1); CP_COMMIT; }

    for (int t = 0; t < T; ++t) {
        if (t + 2 < T) { load_tile(t + 2, (t + 2) & 3); CP_COMMIT; CP_WAIT2; }
        else if (t + 1 < T) { CP_WAIT1; }
        else { CP_WAIT0; }
        __syncthreads();

        int cur = t & 3;
        uint32_t abase = (uint32_t)__cvta_generic_to_shared(As0 + cur * ASTRIDE);
        uint32_t bbase = (uint32_t)__cvta_generic_to_shared(Bs0 + cur * BSTRIDE);
#pragma unroll
        for (int kk = 0; kk < 16; kk += 8) {   // 2 k-groups of 16 halves
            int kk4 = kk * 4;
            uint32_t a[MF][4];
#pragma unroll
            for (int i = 0; i < MF; ++i)
                ldm_x4(a[i], abase + (wm * (BM / 2) + i * 16) * 80 + kk4 + a_lane_off);
            uint32_t bf[NF * 2];
#pragma unroll
            for (int p = 0; p < NF / 2; ++p)
                ldm_x4(&bf[p * 4], bbase + (wn * WN + p * 16) * 80 + kk4 + b_lane_off);
#pragma unroll
            for (int i = 0; i < MF; ++i)
#pragma unroll
                for (int j = 0; j < NF; ++j)
                    mma_f16(acc[i][j], a[i], &bf[j * 2]);
        }
        // no trailing barrier (4-stage ring makes it safe)
    }

    // direct epilogue
#pragma unroll
    for (int i = 0; i < MF; ++i) {
        int r = m0 + wm * (BM / 2) + i * 16 + gid;
#pragma unroll
        for (int j = 0; j < NF; ++j) {
            int cgl = n0 + wn * WN + j * 8 + tig * 2;
            float x0 = acc[i][j][0] * scale, y0 = acc[i][j][1] * scale;
            float x1 = acc[i][j][2] * scale, y1 = acc[i][j][3] * scale;
            if (bias) {
                float bx = bias[cgl], by = bias[cgl + 1];
                x0 += bx; y0 += by; x1 += bx; y1 += by;
            }
            if (HALF_OUT) {
                __half* C = (__half*)Cv + coff;
                *(__half2*)&C[(size_t)r * ldc + cgl] = __floats2half2_rn(x0, y0);
                *(__half2*)&C[(size_t)(r + 8) * ldc + cgl] = __floats2half2_rn(x1, y1);
            } else {
                float* C = (float*)Cv + coff;
                *(float2*)&C[(size_t)r * ldc + cgl] = make_float2(x0, y0);
                *(float2*)&C[(size_t)(r + 8) * ldc + cgl] = make_float2(x1, y1);
            }
        }
    }
}

// ---------------------------------------------------------------------------
// Fused softmax + 8x8 head mix + BN. Register-resident per-warp softmax.
// One block (256 thr) per (b, n).
// ---------------------------------------------------------------------------
__global__ __launch_bounds__(256)
void softmax_mix_kernel(const __half* __restrict__ Sb, __half* __restrict__ Pb,
                        const float* __restrict__ rw, const float* __restrict__ rb,
                        const float* __restrict__ gamma, const float* __restrict__ beta,
                        const float* __restrict__ mean, const float* __restrict__ var) {
    __shared__ __half2 buf[8][512];
    __shared__ float Wm[8][8];
    __shared__ float Cm[8];
    int tid = threadIdx.x;
    int bn = blockIdx.x;
    int b = bn >> 10, n = bn & 1023;

    if (tid < 64) {
        int h = tid >> 3, g = tid & 7;
        float inv = gamma[g] * rsqrtf(var[g] + 1e-3f);
        Wm[h][g] = rw[h * 8 + g] * inv;
        if (h == 0) Cm[g] = (rb[g] - mean[g]) * inv + beta[g];
    }

    int w = tid >> 5, lane = tid & 31;
    size_t base = (size_t)b * 8388608 + (size_t)n * 1024;

    // load head w's row into registers: 4 uint4 = 16 half2 per lane
    const uint4* src = (const uint4*)(Sb + base + (size_t)w * 1048576);
    uint4 raw[4];
#pragma unroll
    for (int j = 0; j < 4; ++j) raw[j] = src[lane + j * 32];
    __half2* vh2 = (__half2*)raw;   // 16 half2, linear in m

    // max (fp16), reduce across warp
    __half2 m2 = vh2[0];
#pragma unroll
    for (int ii = 1; ii < 16; ++ii) m2 = __hmax2(m2, vh2[ii]);
#pragma unroll
    for (int o = 16; o > 0; o >>= 1) {
        uint32_t u = *(uint32_t*)&m2;
        u = __shfl_xor_sync(0xffffffffu, u, o);
        m2 = __hmax2(m2, *(__half2*)&u);
    }
    __half2 mx2 = __half2half2(__hmax(__low2half(m2), __high2half(m2)));
    const __half2 l2e = __float2half2_rn(1.44269504f);

    // exp in fp16 (ex2.f16x2), fp32 sum
    float s = 0.f;
#pragma unroll
    for (int ii = 0; ii < 16; ++ii) {
        __half2 e = h2exp2(__hmul2(__hsub2(vh2[ii], mx2), l2e));
        vh2[ii] = e;
        float2 f = __half22float2(e);
        s += f.x + f.y;
    }
#pragma unroll
    for (int o = 16; o > 0; o >>= 1) s += __shfl_xor_sync(0xffffffffu, s, o);
    __half2 inv2 = __float2half2_rn(1.0f / s);

    // normalize in fp16 (P is fp16 downstream anyway), store to smem
#pragma unroll
    for (int ii = 0; ii < 16; ++ii) vh2[ii] = __hmul2(vh2[ii], inv2);
    uint4* brow = (uint4*)&buf[w][0];
#pragma unroll
    for (int j = 0; j < 4; ++j) brow[lane + j * 32] = raw[j];
    __syncthreads();

    // mix heads in fp32, 4 columns (m = 4*tid..4*tid+3) per thread
    float4 p[8];
#pragma unroll
    for (int h = 0; h < 8; ++h) {
        float2 rawm = ((const float2*)&buf[h][0])[tid];   // 2 half2 = 4 halves
        __half2 lo = *(__half2*)&rawm.x, hi = *(__half2*)&rawm.y;
        float2 f0 = __half22float2(lo), f1 = __half22float2(hi);
        p[h] = make_float4(f0.x, f0.y, f1.x, f1.y);
    }
    float2* gout = (float2*)(Pb + base);                // 8B = 4 halves
#pragma unroll
    for (int g = 0; g < 8; ++g) {
        float c = Cm[g];
        float4 o = make_float4(c, c, c, c);
#pragma unroll
        for (int h = 0; h < 8; ++h) {
            float wv = Wm[h][g];
            o.x += p[h].x * wv; o.y += p[h].y * wv;
            o.z += p[h].z * wv; o.w += p[h].w * wv;
        }
        float2 st;
        *(__half2*)&st.x = __floats2half2_rn(o.x, o.y);
        *(__half2*)&st.y = __floats2half2_rn(o.z, o.w);
        gout[(size_t)g * 262144 + tid] = st;
    }
}

// ---------------------------------------------------------------------------
extern "C" void kernel_launch(void* const* d_in, const int* in_sizes, int n_in,
                              void* d_out, int out_size) {
    const float* q      = (const float*)d_in[0];
    const float* k      = (const float*)d_in[1];
    const float* v      = (const float*)d_in[2];
    const float* conv_w = (const float*)d_in[3];
    const float* rw     = (const float*)d_in[4];
    const float* rb     = (const float*)d_in[5];
    const float* gamma  = (const float*)d_in[6];
    const float* beta   = (const float*)d_in[7];
    const float* mean   = (const float*)d_in[8];
    const float* var    = (const float*)d_in[9];
    const float* pw     = (const float*)d_in[10];
    const float* pb     = (const float*)d_in[11];
    float* out = (float*)d_out;

    float scale = 1.0f / sqrtf((float)HD_);

    __half *qh, *kh, *vh, *vt, *wt, *sS, *pp, *ctx;
    cudaGetSymbolAddress((void**)&qh, g_qh);
    cudaGetSymbolAddress((void**)&kh, g_kh);
    cudaGetSymbolAddress((void**)&vh, g_vh);
    cudaGetSymbolAddress((void**)&vt, g_vt);
    cudaGetSymbolAddress((void**)&wt, g_wt);
    cudaGetSymbolAddress((void**)&sS, g_s);
    cudaGetSymbolAddress((void**)&pp, g_p);
    cudaGetSymbolAddress((void**)&ctx, g_ctx);

    const int SM_QK   = 4 * (128 + 128) * 20 * 4;   // 81920 B
    const int SM_AV   = 4 * (64 + 96) * 20 * 4;     // 51200 B
    const int SM_PROJ = 4 * (128 + 128) * 20 * 4;   // 81920 B
    cudaFuncSetAttribute(f16_gemm_nt<128, 128, true>,
                         cudaFuncAttributeMaxDynamicSharedMemorySize, SM_QK);
    cudaFuncSetAttribute(f16_gemm_nt<64, 96, true>,
                         cudaFuncAttributeMaxDynamicSharedMemorySize, SM_AV);
    cudaFuncSetAttribute(f16_gemm_nt<128, 128, false>,
                         cudaFuncAttributeMaxDynamicSharedMemorySize, SM_PROJ);

    // 1. conv + head split (fp16 outputs)
    conv_heads_kernel<<<dim3(B_ * N_, 3), 256>>>(q, k, v, conv_w);

    // 2. transposes: V(half) -> (B,H,96,N) half, W(float) -> [n][k] half
    transpose_kernel<__half><<<dim3(HD_ / 32, N_ / 32, B_ * H_), dim3(32, 8)>>>(vh, vt, N_, HD_);
    transpose_kernel<float><<<dim3(DIM_ / 32, DIM_ / 32, 1), dim3(32, 8)>>>(pw, wt, DIM_, DIM_);

    // 3. QK^T (scaled) -> S fp16
    f16_gemm_nt<128, 128, true><<<dim3(N_ / 128, N_ / 128, B_ * H_), 128, SM_QK>>>(
        qh, kh, sS, HD_, HD_, HD_, N_,
        (long long)N_ * HD_, (long long)N_ * HD_,
        (long long)H_ * N_ * N_, (long long)N_ * N_,
        scale, nullptr);

    // 4. softmax + head mix + BN -> P fp16
    softmax_mix_kernel<<<B_ * N_, 256>>>(sS, pp, rw, rb, gamma, beta, mean, var);

    // 5. AV -> ctx (B,N,768) fp16. BM=64: 1024 CTAs -> 6.92/SM -> 1.01x tail
    //    (vs BM=128: 512 CTAs -> 3.46/SM -> 1.16x tail). No extra traffic.
    f16_gemm_nt<64, 96, true><<<dim3(1, N_ / 64, B_ * H_), 128, SM_AV>>>(
        pp, vt, ctx, N_, N_, N_, DIM_,
        (long long)N_ * N_, (long long)HD_ * N_,
        (long long)N_ * DIM_, (long long)HD_,
        1.0f, nullptr);

    // 6. projection + bias -> out fp32 (BN=128, round-11 proven config)
    f16_gemm_nt<128, 128, false><<<dim3(DIM_ / 128, (B_ * N_) / 128, 1), 128, SM_PROJ>>>(
        ctx, wt, out, DIM_, DIM_, DIM_, DIM_,
        0LL, 0LL, 0LL, 0LL,
        1.0f, pb);
}